// round 7
// baseline (speedup 1.0000x reference)
#include <cuda_runtime.h>
#include <cuda_bf16.h>
#include <cstdint>

#define DIMN 128
#define NB   16384
#define NN   20000
#define NT   (NB / 128)                 // 128 tile rows/cols
#define NTILES (NT * (NT + 1) / 2)      // 8256 triu tiles
#define EPSL 1e-6f
#define L2E  1.4426950408889634f
#define GRID_NL 148                     // 1 CTA (512 thr) per SM
#define CHUNK ((NTILES + GRID_NL - 1) / GRID_NL)   // 56 tiles per CTA

// smem tile geometry: 128 rows x 128 bf16, padded to 136 bf16 (272 B) per row
#define ROWB 272
#define TILEB (128 * ROWB)              // 34816 B per operand tile
#define DYN_SMEM_NL (3 * TILEB)         // A + 2 stages of B = 104448 B

// ---- scratch (static device globals; no allocation) ----
__device__ __align__(16) __nv_bfloat16 g_p_bf[NN * DIMN];     // full p table, bf16
__device__ __align__(16) __nv_bfloat16 g_pstar_bf[NN * DIMN]; // full p_star table, bf16
__device__ __align__(16) __nv_bfloat16 g_ps_bf[NB * DIMN];    // L2E * p_star[nodes_p_star]
__device__ __align__(16) __nv_bfloat16 g_pp_bf[NB * DIMN];    // L2E * p[nodes_p]
__device__ float2   g_nsbs[NB];        // {|scaled ps row|^2, L2E*beta_p_star}
__device__ float2   g_npbp[NB];        // {|scaled pp row|^2, L2E*beta_p}
__device__ double   g_acc[2];          // [0]=link, [1]=nonlink

static __device__ __forceinline__ float sqrt_approx(float x) {
    float r; asm("sqrt.approx.f32 %0, %1;" : "=f"(r) : "f"(x)); return r;
}
static __device__ __forceinline__ float ex2_approx(float x) {
    float r; asm("ex2.approx.f32 %0, %1;" : "=f"(r) : "f"(x)); return r;
}
static __device__ __forceinline__ uint32_t smem_u32(const void* p) {
    uint32_t a;
    asm("{ .reg .u64 t; cvta.to.shared.u64 t, %1; cvt.u32.u64 %0, t; }" : "=r"(a) : "l"(p));
    return a;
}
static __device__ __forceinline__ void cp_async16(uint32_t dst, const void* src) {
    asm volatile("cp.async.cg.shared.global [%0], [%1], 16;" :: "r"(dst), "l"(src) : "memory");
}
static __device__ __forceinline__ void cp_commit() {
    asm volatile("cp.async.commit_group;" ::: "memory");
}
template <int N> static __device__ __forceinline__ void cp_wait() {
    asm volatile("cp.async.wait_group %0;" :: "n"(N) : "memory");
}
static __device__ __forceinline__ void ldsm_x4(uint32_t& r0, uint32_t& r1,
                                               uint32_t& r2, uint32_t& r3, uint32_t a) {
    asm volatile("ldmatrix.sync.aligned.m8n8.x4.shared.b16 {%0,%1,%2,%3}, [%4];"
                 : "=r"(r0), "=r"(r1), "=r"(r2), "=r"(r3) : "r"(a));
}
static __device__ __forceinline__ void mma16816(float* d, const uint32_t* a,
                                                uint32_t b0, uint32_t b1) {
    asm volatile("mma.sync.aligned.m16n8k16.row.col.f32.bf16.bf16.f32 "
                 "{%0,%1,%2,%3}, {%4,%5,%6,%7}, {%8,%9}, {%0,%1,%2,%3};"
                 : "+f"(d[0]), "+f"(d[1]), "+f"(d[2]), "+f"(d[3])
                 : "r"(a[0]), "r"(a[1]), "r"(a[2]), "r"(a[3]), "r"(b0), "r"(b1));
}
static __device__ __forceinline__ float2 bf2f(uint32_t u) {
    __nv_bfloat162 h = *reinterpret_cast<__nv_bfloat162*>(&u);
    return __bfloat1622float2(h);
}

// One epilogue slice: 4 elements of the previous tile's accumulators.
// rv[2]: {ns,bs} for rows r_lo, r_lo+8 of strip mi. d: acc[mi][n][0..3].
static __device__ __forceinline__ void epi_slice(
    float& nls, const float* d, const float2 rv0, const float2 rv1,
    int pc0, int col0w, int n, int lane, bool pdiag, int r_lo) {
    const int c0 = pc0 + col0w + n * 8 + 2 * (lane & 3);
    const float2 cv0 = __ldg(&g_npbp[c0]);
    const float2 cv1 = __ldg(&g_npbp[c0 + 1]);
    if (!pdiag) {
        nls += ex2_approx(rv0.y + cv0.y - sqrt_approx(fmaxf(rv0.x + cv0.x - 2.f * d[0], 0.f)));
        nls += ex2_approx(rv0.y + cv1.y - sqrt_approx(fmaxf(rv0.x + cv1.x - 2.f * d[1], 0.f)));
        nls += ex2_approx(rv1.y + cv0.y - sqrt_approx(fmaxf(rv1.x + cv0.x - 2.f * d[2], 0.f)));
        nls += ex2_approx(rv1.y + cv1.y - sqrt_approx(fmaxf(rv1.x + cv1.x - 2.f * d[3], 0.f)));
    } else {
        float w;
        w = ex2_approx(rv0.y + cv0.y - sqrt_approx(fmaxf(rv0.x + cv0.x - 2.f * d[0], 0.f)));
        if (r_lo < c0) nls += w;
        w = ex2_approx(rv0.y + cv1.y - sqrt_approx(fmaxf(rv0.x + cv1.x - 2.f * d[1], 0.f)));
        if (r_lo < c0 + 1) nls += w;
        w = ex2_approx(rv1.y + cv0.y - sqrt_approx(fmaxf(rv1.x + cv0.x - 2.f * d[2], 0.f)));
        if (r_lo + 8 < c0) nls += w;
        w = ex2_approx(rv1.y + cv1.y - sqrt_approx(fmaxf(rv1.x + cv1.x - 2.f * d[3], 0.f)));
        if (r_lo + 8 < c0 + 1) nls += w;
    }
}

// ---------------- kernels ----------------
// convert full p / p_star tables to bf16 (one warp per row per table); zero accumulators
__global__ void k_prep(const float* __restrict__ p, const float* __restrict__ pstar) {
    if (blockIdx.x == 0 && threadIdx.x == 0) { g_acc[0] = 0.0; g_acc[1] = 0.0; }
    int w    = blockIdx.x * 8 + (threadIdx.x >> 5);
    int lane = threadIdx.x & 31;
    int row  = w >> 1;
    if (row >= NN) return;
    const float* src = (w & 1) ? pstar : p;
    __nv_bfloat16* dst = (w & 1) ? g_pstar_bf : g_p_bf;
    float4 v = ((const float4*)(src + (size_t)row * DIMN))[lane];
    __nv_bfloat162* d = (__nv_bfloat162*)(dst + (size_t)row * DIMN);
    d[2 * lane + 0] = __floats2bfloat162_rn(v.x, v.y);
    d[2 * lane + 1] = __floats2bfloat162_rn(v.z, v.w);
}

// gather rows (from bf16 tables), scale by L2E, store scaled bf16 + {norm,beta} pairs
__global__ void k_gather(const int* __restrict__ nps, const int* __restrict__ npp,
                         const float* __restrict__ beta_p, const float* __restrict__ beta_ps) {
    int row  = blockIdx.x * 8 + (threadIdx.x >> 5);
    int lane = threadIdx.x & 31;
    if (row >= NB) return;
    int is = nps[row], ip = npp[row];
    uint2 rs = ((const uint2*)(g_pstar_bf + (size_t)is * DIMN))[lane];
    uint2 rp = ((const uint2*)(g_p_bf     + (size_t)ip * DIMN))[lane];

    float2 s0 = bf2f(rs.x), s1 = bf2f(rs.y), p0 = bf2f(rp.x), p1 = bf2f(rp.y);
    __nv_bfloat162 os0 = __floats2bfloat162_rn(s0.x * L2E, s0.y * L2E);
    __nv_bfloat162 os1 = __floats2bfloat162_rn(s1.x * L2E, s1.y * L2E);
    __nv_bfloat162 op0 = __floats2bfloat162_rn(p0.x * L2E, p0.y * L2E);
    __nv_bfloat162 op1 = __floats2bfloat162_rn(p1.x * L2E, p1.y * L2E);
    ((__nv_bfloat162*)(g_ps_bf + (size_t)row * DIMN))[2 * lane + 0] = os0;
    ((__nv_bfloat162*)(g_ps_bf + (size_t)row * DIMN))[2 * lane + 1] = os1;
    ((__nv_bfloat162*)(g_pp_bf + (size_t)row * DIMN))[2 * lane + 0] = op0;
    ((__nv_bfloat162*)(g_pp_bf + (size_t)row * DIMN))[2 * lane + 1] = op1;

    float2 a0 = __bfloat1622float2(os0), a1 = __bfloat1622float2(os1);
    float2 b0 = __bfloat1622float2(op0), b1 = __bfloat1622float2(op1);
    float a = a0.x*a0.x + a0.y*a0.y + a1.x*a1.x + a1.y*a1.y;
    float b = b0.x*b0.x + b0.y*b0.y + b1.x*b1.x + b1.y*b1.y;
#pragma unroll
    for (int o = 16; o; o >>= 1) {
        a += __shfl_xor_sync(0xffffffffu, a, o);
        b += __shfl_xor_sync(0xffffffffu, b, o);
    }
    if (lane == 0) {
        g_nsbs[row] = make_float2(a, beta_ps[is] * L2E);
        g_npbp[row] = make_float2(b, beta_p[ip] * L2E);
    }
}

// Link term: 8 lanes per edge, 4 edges per warp in parallel (3-deep shfl reduce).
__global__ void k_link(const int* __restrict__ edges, int E,
                       const float* __restrict__ beta_p, const float* __restrict__ beta_ps) {
    __shared__ float wsum[8];
    const int gw   = (blockIdx.x * blockDim.x + threadIdx.x) >> 5;
    const int wid  = threadIdx.x >> 5;
    const int lane = threadIdx.x & 31;
    const int nw   = (gridDim.x * blockDim.x) >> 5;
    const int sub  = lane & 7;
    const int eq   = lane >> 3;

    float local = 0.f;
    for (int base = gw * 4; base < E; base += nw * 4) {
        const int e = base + eq;
        const bool valid = (e < E);
        float s = 0.f;
        int e0 = 0, e1 = 0;
        if (valid) {
            e0 = edges[e]; e1 = edges[E + e];
            const uint4* ra = (const uint4*)(g_p_bf     + (size_t)e0 * DIMN);
            const uint4* rb = (const uint4*)(g_pstar_bf + (size_t)e1 * DIMN);
            const uint4 a0 = ra[2 * sub], a1 = ra[2 * sub + 1];
            const uint4 b0 = rb[2 * sub], b1 = rb[2 * sub + 1];
#pragma unroll
            for (int w = 0; w < 4; w++) {
                const float2 fa = bf2f((&a0.x)[w]), fb = bf2f((&b0.x)[w]);
                const float dx = fa.x - fb.x + EPSL, dy = fa.y - fb.y + EPSL;
                s += dx * dx + dy * dy;
            }
#pragma unroll
            for (int w = 0; w < 4; w++) {
                const float2 fa = bf2f((&a1.x)[w]), fb = bf2f((&b1.x)[w]);
                const float dx = fa.x - fb.x + EPSL, dy = fa.y - fb.y + EPSL;
                s += dx * dx + dy * dy;
            }
        }
        s += __shfl_xor_sync(0xffffffffu, s, 1);
        s += __shfl_xor_sync(0xffffffffu, s, 2);
        s += __shfl_xor_sync(0xffffffffu, s, 4);
        if (valid && sub == 0)
            local += beta_ps[e0] + beta_p[e1] - sqrt_approx(s);
    }
#pragma unroll
    for (int o = 16; o; o >>= 1) local += __shfl_xor_sync(0xffffffffu, local, o);
    if (lane == 0) wsum[wid] = local;
    __syncthreads();
    if (threadIdx.x == 0) {
        float s = 0.f;
#pragma unroll
        for (int w = 0; w < 8; w++) s += wsum[w];
        atomicAdd(&g_acc[0], (double)s);
    }
}

// Non-link: persistent mma.sync bf16 GEMM, software-pipelined epilogue:
// previous tile's epilogue slices are interleaved between current tile's MMA
// k-steps so tensor and MUFU pipes run concurrently within every warp.
// 16 warps x 32x32 strips; A persists across same-row tiles; B double-buffered.
__global__ __launch_bounds__(512, 1)
void k_nonlink_mma() {
    extern __shared__ __align__(16) char smem[];
    __shared__ float warpsum[16];
    const int tid  = threadIdx.x;
    const int wid  = tid >> 5;
    const int lane = tid & 31;
    const uint32_t sbase = smem_u32(smem);
    const uint32_t abase = sbase;
    const uint32_t bst[2] = { sbase + TILEB, sbase + 2 * TILEB };

    const int row0w = (wid & 3) * 32;     // 4 M-strips of 32
    const int col0w = (wid >> 2) * 32;    // 4 N-strips of 32
    const uint32_t lm_off = (uint32_t)(lane & 15) * ROWB + (uint32_t)(lane >> 4) * 16;

    float nls = 0.f;

    const int t0 = blockIdx.x * CHUNK;
    const int t1 = (t0 + CHUNK < NTILES) ? (t0 + CHUNK) : NTILES;

    float accP[2][4][4];                  // previous tile's accumulators
    int  pr0 = 0, pc0 = 0;
    bool pdiag = false, pvalid = false;

    if (t0 < NTILES) {
        // decode t0 -> (by, bx) by row scan
        int by = 0, rem = t0;
        while (rem >= NT - by) { rem -= NT - by; by++; }
        int bx = by + rem;

        // prologue: A(by) + B(bx) into stage 0
#pragma unroll
        for (int it = 0; it < 4; it++) {
            const int c = tid + (it << 9);
            const int m = c >> 4, q = c & 15;
            cp_async16(abase + (uint32_t)m * ROWB + (uint32_t)q * 16,
                       (const char*)g_ps_bf + ((size_t)((by << 7) + m) << 8) + ((size_t)q << 4));
            cp_async16(bst[0] + (uint32_t)m * ROWB + (uint32_t)q * 16,
                       (const char*)g_pp_bf + ((size_t)((bx << 7) + m) << 8) + ((size_t)q << 4));
        }
        cp_commit();

        int s = 0;
        for (int t = t0; t < t1; t++) {
            int nbx = bx + 1, nby = by;
            if (nbx >= NT) { nby = by + 1; nbx = nby; }
            const bool have_next = (t + 1 < t1);

            if (have_next) {
#pragma unroll
                for (int it = 0; it < 4; it++) {
                    const int c = tid + (it << 9);
                    const int m = c >> 4, q = c & 15;
                    cp_async16(bst[1 - s] + (uint32_t)m * ROWB + (uint32_t)q * 16,
                               (const char*)g_pp_bf + ((size_t)((nbx << 7) + m) << 8) + ((size_t)q << 4));
                }
            }
            cp_commit();
            cp_wait<1>();       // current B + A resident
            __syncthreads();

            // row-side epilogue values for the previous tile (one load per tile)
            float2 rv[2][2];
            int prl = 0;
            if (pvalid) {
                prl = pr0 + row0w + (lane >> 2);
                rv[0][0] = __ldg(&g_nsbs[prl]);      rv[0][1] = __ldg(&g_nsbs[prl + 8]);
                rv[1][0] = __ldg(&g_nsbs[prl + 16]); rv[1][1] = __ldg(&g_nsbs[prl + 24]);
            }

            const uint32_t aw = abase  + (uint32_t)row0w * ROWB + lm_off;
            const uint32_t bw = bst[s] + (uint32_t)col0w * ROWB + lm_off;

            float acc[2][4][4];
#pragma unroll
            for (int mi = 0; mi < 2; mi++)
#pragma unroll
                for (int n = 0; n < 4; n++)
#pragma unroll
                    for (int v = 0; v < 4; v++) acc[mi][n][v] = 0.f;

            // fused k-loop: MMA(t) interleaved with epilogue slices of tile t-1
#pragma unroll
            for (int k = 0; k < 8; k++) {
                uint32_t a[2][4], bf[2][4];
#pragma unroll
                for (int mi = 0; mi < 2; mi++)
                    ldsm_x4(a[mi][0], a[mi][1], a[mi][2], a[mi][3],
                            aw + (uint32_t)mi * 16 * ROWB + (uint32_t)k * 32);
#pragma unroll
                for (int nj = 0; nj < 2; nj++)
                    ldsm_x4(bf[nj][0], bf[nj][1], bf[nj][2], bf[nj][3],
                            bw + (uint32_t)nj * 16 * ROWB + (uint32_t)k * 32);
#pragma unroll
                for (int mi = 0; mi < 2; mi++)
#pragma unroll
                    for (int n = 0; n < 4; n++) {
                        const int nj = n >> 1;
                        if ((n & 1) == 0) mma16816(acc[mi][n], a[mi], bf[nj][0], bf[nj][2]);
                        else              mma16816(acc[mi][n], a[mi], bf[nj][1], bf[nj][3]);
                    }
                // epilogue slice k of previous tile: (mi, n) = (k>>2, k&3)
                if (pvalid) {
                    const int emi = k >> 2, en = k & 3;
                    epi_slice(nls, accP[emi][en], rv[emi][0], rv[emi][1],
                              pc0, col0w, en, lane, pdiag, prl + emi * 16);
                }
            }
            __syncthreads();    // all warps done reading A + B stage s

            if (have_next && nby != by) {   // A refill for next row
#pragma unroll
                for (int it = 0; it < 4; it++) {
                    const int c = tid + (it << 9);
                    const int m = c >> 4, q = c & 15;
                    cp_async16(abase + (uint32_t)m * ROWB + (uint32_t)q * 16,
                               (const char*)g_ps_bf + ((size_t)((nby << 7) + m) << 8) + ((size_t)q << 4));
                }
                cp_commit();
            }

            // stash current tile for next iteration's interleaved epilogue
#pragma unroll
            for (int mi = 0; mi < 2; mi++)
#pragma unroll
                for (int n = 0; n < 4; n++)
#pragma unroll
                    for (int v = 0; v < 4; v++) accP[mi][n][v] = acc[mi][n][v];
            pr0 = by << 7; pc0 = bx << 7; pdiag = (bx == by); pvalid = true;
            by = nby; bx = nbx; s ^= 1;
        }

        // drain: epilogue of the final tile
        {
            const int prl = pr0 + row0w + (lane >> 2);
            float2 rv[2][2];
            rv[0][0] = __ldg(&g_nsbs[prl]);      rv[0][1] = __ldg(&g_nsbs[prl + 8]);
            rv[1][0] = __ldg(&g_nsbs[prl + 16]); rv[1][1] = __ldg(&g_nsbs[prl + 24]);
#pragma unroll
            for (int k = 0; k < 8; k++) {
                const int emi = k >> 2, en = k & 3;
                epi_slice(nls, accP[emi][en], rv[emi][0], rv[emi][1],
                          pc0, col0w, en, lane, pdiag, prl + emi * 16);
            }
        }
    }

#pragma unroll
    for (int o = 16; o; o >>= 1) nls += __shfl_xor_sync(0xffffffffu, nls, o);
    if (lane == 0) warpsum[wid] = nls;
    __syncthreads();
    if (tid == 0) {
        float sum = 0.f;
#pragma unroll
        for (int w = 0; w < 16; w++) sum += warpsum[w];
        atomicAdd(&g_acc[1], (double)sum);
    }
}

__global__ void k_final(float* out) {
    out[0] = (float)(g_acc[1] - g_acc[0]);   // -(link - nonlink)
}

extern "C" void kernel_launch(void* const* d_in, const int* in_sizes, int n_in,
                              void* d_out, int out_size) {
    const int*   edges   = (const int*)d_in[0];
    const int*   nps     = (const int*)d_in[1];   // nodes_p_star
    const int*   npp     = (const int*)d_in[2];   // nodes_p
    const float* beta_p  = (const float*)d_in[3];
    const float* beta_ps = (const float*)d_in[4];
    const float* p       = (const float*)d_in[5];
    const float* pstar   = (const float*)d_in[6];
    float* out = (float*)d_out;
    int E = in_sizes[0] / 2;

    cudaFuncSetAttribute(k_nonlink_mma, cudaFuncAttributeMaxDynamicSharedMemorySize, DYN_SMEM_NL);

    k_prep<<<(2 * NN + 7) / 8, 256>>>(p, pstar);
    k_gather<<<NB / 8, 256>>>(nps, npp, beta_p, beta_ps);
    k_link<<<2048, 256>>>(edges, E, beta_p, beta_ps);
    k_nonlink_mma<<<GRID_NL, 512, DYN_SMEM_NL>>>();
    k_final<<<1, 1>>>(out);
}

// round 9
// speedup vs baseline: 1.0884x; 1.0884x over previous
#include <cuda_runtime.h>
#include <cuda_bf16.h>
#include <cstdint>

#define DIMN 128
#define NB   16384
#define NN   20000
#define NT   (NB / 128)                 // 128 tile rows/cols
#define NTILES (NT * (NT + 1) / 2)      // 8256 triu tiles
#define EPSL 1e-6f
#define L2E  1.4426950408889634f
#define GRID_NL 296                     // 2 CTAs per SM
#define CHUNK ((NTILES + GRID_NL - 1) / GRID_NL)   // 28 tiles per CTA

// smem tile geometry: 128 rows x 128 bf16, padded to 136 bf16 (272 B) per row
#define ROWB 272
#define TILEB (128 * ROWB)              // 34816 B per operand tile
#define DYN_SMEM_NL (3 * TILEB)         // A + 2 stages of B = 104448 B

// ---- scratch (static device globals; no allocation) ----
__device__ __align__(16) __nv_bfloat16 g_p_bf[NN * DIMN];     // full p table, bf16
__device__ __align__(16) __nv_bfloat16 g_pstar_bf[NN * DIMN]; // full p_star table, bf16
__device__ __align__(16) __nv_bfloat16 g_ps_bf[NB * DIMN];    // L2E * p_star[nodes_p_star]
__device__ __align__(16) __nv_bfloat16 g_pp_bf[NB * DIMN];    // L2E * p[nodes_p]
__device__ float2   g_nsbs[NB];        // {|scaled ps row|^2, L2E*beta_p_star}
__device__ float2   g_npbp[NB];        // {|scaled pp row|^2, L2E*beta_p}
__device__ double   g_acc[2];          // [0]=link, [1]=nonlink

static __device__ __forceinline__ float sqrt_approx(float x) {
    float r; asm("sqrt.approx.f32 %0, %1;" : "=f"(r) : "f"(x)); return r;
}
static __device__ __forceinline__ float ex2_approx(float x) {
    float r; asm("ex2.approx.f32 %0, %1;" : "=f"(r) : "f"(x)); return r;
}
static __device__ __forceinline__ uint32_t smem_u32(const void* p) {
    uint32_t a;
    asm("{ .reg .u64 t; cvta.to.shared.u64 t, %1; cvt.u32.u64 %0, t; }" : "=r"(a) : "l"(p));
    return a;
}
static __device__ __forceinline__ void cp_async16(uint32_t dst, const void* src) {
    asm volatile("cp.async.cg.shared.global [%0], [%1], 16;" :: "r"(dst), "l"(src) : "memory");
}
static __device__ __forceinline__ void cp_commit() {
    asm volatile("cp.async.commit_group;" ::: "memory");
}
template <int N> static __device__ __forceinline__ void cp_wait() {
    asm volatile("cp.async.wait_group %0;" :: "n"(N) : "memory");
}
static __device__ __forceinline__ void ldsm_x4(uint32_t& r0, uint32_t& r1,
                                               uint32_t& r2, uint32_t& r3, uint32_t a) {
    asm volatile("ldmatrix.sync.aligned.m8n8.x4.shared.b16 {%0,%1,%2,%3}, [%4];"
                 : "=r"(r0), "=r"(r1), "=r"(r2), "=r"(r3) : "r"(a));
}
static __device__ __forceinline__ void mma16816(float* d, const uint32_t* a,
                                                uint32_t b0, uint32_t b1) {
    asm volatile("mma.sync.aligned.m16n8k16.row.col.f32.bf16.bf16.f32 "
                 "{%0,%1,%2,%3}, {%4,%5,%6,%7}, {%8,%9}, {%0,%1,%2,%3};"
                 : "+f"(d[0]), "+f"(d[1]), "+f"(d[2]), "+f"(d[3])
                 : "r"(a[0]), "r"(a[1]), "r"(a[2]), "r"(a[3]), "r"(b0), "r"(b1));
}
static __device__ __forceinline__ float2 bf2f(uint32_t u) {
    __nv_bfloat162 h = *reinterpret_cast<__nv_bfloat162*>(&u);
    return __bfloat1622float2(h);
}

// One epilogue slice: 4 elements (rows r_lo, r_lo+8 x cols c0, c0+1).
// All values pre-scaled by L2E: w = ex2(bsum - sqrt(nsum - 2g)).
static __device__ __forceinline__ void epi_slice(
    float& nls, const float* d, const float2 rv0, const float2 rv1,
    int c0, bool diag, int r_lo) {
    const float2 cv0 = __ldg(&g_npbp[c0]);
    const float2 cv1 = __ldg(&g_npbp[c0 + 1]);
    if (!diag) {
        nls += ex2_approx(rv0.y + cv0.y - sqrt_approx(fmaxf(rv0.x + cv0.x - 2.f * d[0], 0.f)));
        nls += ex2_approx(rv0.y + cv1.y - sqrt_approx(fmaxf(rv0.x + cv1.x - 2.f * d[1], 0.f)));
        nls += ex2_approx(rv1.y + cv0.y - sqrt_approx(fmaxf(rv1.x + cv0.x - 2.f * d[2], 0.f)));
        nls += ex2_approx(rv1.y + cv1.y - sqrt_approx(fmaxf(rv1.x + cv1.x - 2.f * d[3], 0.f)));
    } else {
        float w;
        w = ex2_approx(rv0.y + cv0.y - sqrt_approx(fmaxf(rv0.x + cv0.x - 2.f * d[0], 0.f)));
        if (r_lo < c0) nls += w;
        w = ex2_approx(rv0.y + cv1.y - sqrt_approx(fmaxf(rv0.x + cv1.x - 2.f * d[1], 0.f)));
        if (r_lo < c0 + 1) nls += w;
        w = ex2_approx(rv1.y + cv0.y - sqrt_approx(fmaxf(rv1.x + cv0.x - 2.f * d[2], 0.f)));
        if (r_lo + 8 < c0) nls += w;
        w = ex2_approx(rv1.y + cv1.y - sqrt_approx(fmaxf(rv1.x + cv1.x - 2.f * d[3], 0.f)));
        if (r_lo + 8 < c0 + 1) nls += w;
    }
}

// ---------------- kernels ----------------
// convert full p / p_star tables to bf16 (one warp per row per table); zero accumulators
__global__ void k_prep(const float* __restrict__ p, const float* __restrict__ pstar) {
    if (blockIdx.x == 0 && threadIdx.x == 0) { g_acc[0] = 0.0; g_acc[1] = 0.0; }
    int w    = blockIdx.x * 8 + (threadIdx.x >> 5);
    int lane = threadIdx.x & 31;
    int row  = w >> 1;
    if (row >= NN) return;
    const float* src = (w & 1) ? pstar : p;
    __nv_bfloat16* dst = (w & 1) ? g_pstar_bf : g_p_bf;
    float4 v = ((const float4*)(src + (size_t)row * DIMN))[lane];
    __nv_bfloat162* d = (__nv_bfloat162*)(dst + (size_t)row * DIMN);
    d[2 * lane + 0] = __floats2bfloat162_rn(v.x, v.y);
    d[2 * lane + 1] = __floats2bfloat162_rn(v.z, v.w);
}

// gather rows (from bf16 tables), scale by L2E, store scaled bf16 + {norm,beta} pairs
__global__ void k_gather(const int* __restrict__ nps, const int* __restrict__ npp,
                         const float* __restrict__ beta_p, const float* __restrict__ beta_ps) {
    int row  = blockIdx.x * 8 + (threadIdx.x >> 5);
    int lane = threadIdx.x & 31;
    if (row >= NB) return;
    int is = nps[row], ip = npp[row];
    uint2 rs = ((const uint2*)(g_pstar_bf + (size_t)is * DIMN))[lane];
    uint2 rp = ((const uint2*)(g_p_bf     + (size_t)ip * DIMN))[lane];

    float2 s0 = bf2f(rs.x), s1 = bf2f(rs.y), p0 = bf2f(rp.x), p1 = bf2f(rp.y);
    __nv_bfloat162 os0 = __floats2bfloat162_rn(s0.x * L2E, s0.y * L2E);
    __nv_bfloat162 os1 = __floats2bfloat162_rn(s1.x * L2E, s1.y * L2E);
    __nv_bfloat162 op0 = __floats2bfloat162_rn(p0.x * L2E, p0.y * L2E);
    __nv_bfloat162 op1 = __floats2bfloat162_rn(p1.x * L2E, p1.y * L2E);
    ((__nv_bfloat162*)(g_ps_bf + (size_t)row * DIMN))[2 * lane + 0] = os0;
    ((__nv_bfloat162*)(g_ps_bf + (size_t)row * DIMN))[2 * lane + 1] = os1;
    ((__nv_bfloat162*)(g_pp_bf + (size_t)row * DIMN))[2 * lane + 0] = op0;
    ((__nv_bfloat162*)(g_pp_bf + (size_t)row * DIMN))[2 * lane + 1] = op1;

    float2 a0 = __bfloat1622float2(os0), a1 = __bfloat1622float2(os1);
    float2 b0 = __bfloat1622float2(op0), b1 = __bfloat1622float2(op1);
    float a = a0.x*a0.x + a0.y*a0.y + a1.x*a1.x + a1.y*a1.y;
    float b = b0.x*b0.x + b0.y*b0.y + b1.x*b1.x + b1.y*b1.y;
#pragma unroll
    for (int o = 16; o; o >>= 1) {
        a += __shfl_xor_sync(0xffffffffu, a, o);
        b += __shfl_xor_sync(0xffffffffu, b, o);
    }
    if (lane == 0) {
        g_nsbs[row] = make_float2(a, beta_ps[is] * L2E);
        g_npbp[row] = make_float2(b, beta_p[ip] * L2E);
    }
}

// Link term: 8 lanes per edge, 4 edges per warp in parallel (3-deep shfl reduce).
__global__ void k_link(const int* __restrict__ edges, int E,
                       const float* __restrict__ beta_p, const float* __restrict__ beta_ps) {
    __shared__ float wsum[8];
    const int gw   = (blockIdx.x * blockDim.x + threadIdx.x) >> 5;
    const int wid  = threadIdx.x >> 5;
    const int lane = threadIdx.x & 31;
    const int nw   = (gridDim.x * blockDim.x) >> 5;
    const int sub  = lane & 7;
    const int eq   = lane >> 3;

    float local = 0.f;
    for (int base = gw * 4; base < E; base += nw * 4) {
        const int e = base + eq;
        const bool valid = (e < E);
        float s = 0.f;
        int e0 = 0, e1 = 0;
        if (valid) {
            e0 = edges[e]; e1 = edges[E + e];
            const uint4* ra = (const uint4*)(g_p_bf     + (size_t)e0 * DIMN);
            const uint4* rb = (const uint4*)(g_pstar_bf + (size_t)e1 * DIMN);
            const uint4 a0 = ra[2 * sub], a1 = ra[2 * sub + 1];
            const uint4 b0 = rb[2 * sub], b1 = rb[2 * sub + 1];
#pragma unroll
            for (int w = 0; w < 4; w++) {
                const float2 fa = bf2f((&a0.x)[w]), fb = bf2f((&b0.x)[w]);
                const float dx = fa.x - fb.x + EPSL, dy = fa.y - fb.y + EPSL;
                s += dx * dx + dy * dy;
            }
#pragma unroll
            for (int w = 0; w < 4; w++) {
                const float2 fa = bf2f((&a1.x)[w]), fb = bf2f((&b1.x)[w]);
                const float dx = fa.x - fb.x + EPSL, dy = fa.y - fb.y + EPSL;
                s += dx * dx + dy * dy;
            }
        }
        s += __shfl_xor_sync(0xffffffffu, s, 1);
        s += __shfl_xor_sync(0xffffffffu, s, 2);
        s += __shfl_xor_sync(0xffffffffu, s, 4);
        if (valid && sub == 0)
            local += beta_ps[e0] + beta_p[e1] - sqrt_approx(s);
    }
#pragma unroll
    for (int o = 16; o; o >>= 1) local += __shfl_xor_sync(0xffffffffu, local, o);
    if (lane == 0) wsum[wid] = local;
    __syncthreads();
    if (threadIdx.x == 0) {
        float s = 0.f;
#pragma unroll
        for (int w = 0; w < 8; w++) s += wsum[w];
        atomicAdd(&g_acc[0], (double)s);
    }
}

// Non-link: persistent mma.sync bf16 GEMM (R6 structure: 8 warps x 32x64, 2 CTAs/SM,
// A persists across same-row tiles, B double-buffered) + half-tile software pipeline:
// while the k-loop computes half h of the current tile, the epilogue of the previous
// 32x32 half runs interleaved (one 4-element slice per k-step), so tensor and MUFU
// pipes run concurrently inside every warp.
__global__ __launch_bounds__(256, 2)
void k_nonlink_mma() {
    extern __shared__ __align__(16) char smem[];
    __shared__ float warpsum[8];
    const int tid  = threadIdx.x;
    const int wid  = tid >> 5;
    const int lane = tid & 31;
    const uint32_t sbase = smem_u32(smem);
    const uint32_t abase = sbase;
    const uint32_t bst[2] = { sbase + TILEB, sbase + 2 * TILEB };

    const int row0w = (wid & 3) * 32;     // 4 M-strips of 32
    const int col0w = (wid >> 2) * 64;    // 2 N-strips of 64 (split into 2 halves of 32)
    const uint32_t lm_off = (uint32_t)(lane & 15) * ROWB + (uint32_t)(lane >> 4) * 16;

    float nls = 0.f;

    const int t0 = blockIdx.x * CHUNK;
    const int t1 = (t0 + CHUNK < NTILES) ? (t0 + CHUNK) : NTILES;

    // ping-pong accumulators: accH[0] = half0 of current tile, accH[1] = half1
    // (accH[1] of tile t is the "previous half" during phase 0 of tile t+1)
    float accH[2][2][4][4];
    // carried prev-half epilogue state (always refers to accH[1] of the last tile)
    float2 rvP[4];
    int  prl = 0, pcb = 0;
    bool pdiag = false, pvalid = false;

    if (t0 < t1) {
        int by = 0, rem = t0;
        while (rem >= NT - by) { rem -= NT - by; by++; }
        int bx = by + rem;

        // prologue: A(by) + B(bx) into stage 0
#pragma unroll
        for (int it = 0; it < 8; it++) {
            const int c = tid + (it << 8);
            const int m = c >> 4, q = c & 15;
            cp_async16(abase + (uint32_t)m * ROWB + (uint32_t)q * 16,
                       (const char*)g_ps_bf + ((size_t)((by << 7) + m) << 8) + ((size_t)q << 4));
            cp_async16(bst[0] + (uint32_t)m * ROWB + (uint32_t)q * 16,
                       (const char*)g_pp_bf + ((size_t)((bx << 7) + m) << 8) + ((size_t)q << 4));
        }
        cp_commit();

        int s = 0;
        for (int t = t0; t < t1; t++) {
            int nbx = bx + 1, nby = by;
            if (nbx >= NT) { nby = by + 1; nbx = nby; }
            const bool have_next = (t + 1 < t1);

            if (have_next) {
#pragma unroll
                for (int it = 0; it < 8; it++) {
                    const int c = tid + (it << 8);
                    const int m = c >> 4, q = c & 15;
                    cp_async16(bst[1 - s] + (uint32_t)m * ROWB + (uint32_t)q * 16,
                               (const char*)g_pp_bf + ((size_t)((nbx << 7) + m) << 8) + ((size_t)q << 4));
                }
            }
            cp_commit();
            cp_wait<1>();
            __syncthreads();

            // row-side epilogue values for the CURRENT tile's row
            const int crl = (by << 7) + row0w + (lane >> 2);
            float2 rvC[4];
            rvC[0] = __ldg(&g_nsbs[crl]);      rvC[1] = __ldg(&g_nsbs[crl + 8]);
            rvC[2] = __ldg(&g_nsbs[crl + 16]); rvC[3] = __ldg(&g_nsbs[crl + 24]);

            const uint32_t aw = abase  + (uint32_t)row0w * ROWB + lm_off;
            const uint32_t bw = bst[s] + (uint32_t)col0w * ROWB + lm_off;
            const bool cdiag = (bx == by);
            const int  ccb0  = (bx << 7) + col0w + 2 * (lane & 3);   // current half0 col base

#pragma unroll
            for (int h = 0; h < 2; h++) {
                float (*cur)[4][4] = accH[h];
#pragma unroll
                for (int mi = 0; mi < 2; mi++)
#pragma unroll
                    for (int n = 0; n < 4; n++)
#pragma unroll
                        for (int v = 0; v < 4; v++) cur[mi][n][v] = 0.f;

                const uint32_t bwh = bw + (uint32_t)h * 32 * ROWB;
                const bool do_epi = (h == 1) || pvalid;

#pragma unroll
                for (int k = 0; k < 8; k++) {
                    uint32_t a[2][4], bf[2][4];
#pragma unroll
                    for (int mi = 0; mi < 2; mi++)
                        ldsm_x4(a[mi][0], a[mi][1], a[mi][2], a[mi][3],
                                aw + (uint32_t)mi * 16 * ROWB + (uint32_t)k * 32);
#pragma unroll
                    for (int nj = 0; nj < 2; nj++)
                        ldsm_x4(bf[nj][0], bf[nj][1], bf[nj][2], bf[nj][3],
                                bwh + (uint32_t)nj * 16 * ROWB + (uint32_t)k * 32);
#pragma unroll
                    for (int mi = 0; mi < 2; mi++)
#pragma unroll
                        for (int n = 0; n < 4; n++) {
                            const int nj = n >> 1;
                            if ((n & 1) == 0) mma16816(cur[mi][n], a[mi], bf[nj][0], bf[nj][2]);
                            else              mma16816(cur[mi][n], a[mi], bf[nj][1], bf[nj][3]);
                        }
                    // interleaved epilogue slice of the previous 32x32 half
                    if (do_epi) {
                        const int emi = k >> 2, en = k & 3;
                        if (h == 0) {
                            epi_slice(nls, accH[1][emi][en], rvP[emi * 2], rvP[emi * 2 + 1],
                                      pcb + en * 8, pdiag, prl + emi * 16);
                        } else {
                            epi_slice(nls, accH[0][emi][en], rvC[emi * 2], rvC[emi * 2 + 1],
                                      ccb0 + en * 8, cdiag, crl + emi * 16);
                        }
                    }
                }
            }
            __syncthreads();    // all warps done with A + B stage s

            if (have_next && nby != by) {   // A refill for next row
#pragma unroll
                for (int it = 0; it < 8; it++) {
                    const int c = tid + (it << 8);
                    const int m = c >> 4, q = c & 15;
                    cp_async16(abase + (uint32_t)m * ROWB + (uint32_t)q * 16,
                               (const char*)g_ps_bf + ((size_t)((nby << 7) + m) << 8) + ((size_t)q << 4));
                }
                cp_commit();
            }

            // carry prev-half state = current tile's half1
            rvP[0] = rvC[0]; rvP[1] = rvC[1]; rvP[2] = rvC[2]; rvP[3] = rvC[3];
            prl = crl; pcb = ccb0 + 32; pdiag = cdiag; pvalid = true;
            by = nby; bx = nbx; s ^= 1;
        }

        // drain: epilogue of the final tile's half1
#pragma unroll
        for (int k = 0; k < 8; k++) {
            const int emi = k >> 2, en = k & 3;
            epi_slice(nls, accH[1][emi][en], rvP[emi * 2], rvP[emi * 2 + 1],
                      pcb + en * 8, pdiag, prl + emi * 16);
        }
    }

#pragma unroll
    for (int o = 16; o; o >>= 1) nls += __shfl_xor_sync(0xffffffffu, nls, o);
    if (lane == 0) warpsum[wid] = nls;
    __syncthreads();
    if (tid == 0) {
        float sum = 0.f;
#pragma unroll
        for (int w = 0; w < 8; w++) sum += warpsum[w];
        atomicAdd(&g_acc[1], (double)sum);
    }
}

__global__ void k_final(float* out) {
    out[0] = (float)(g_acc[1] - g_acc[0]);   // -(link - nonlink)
}

extern "C" void kernel_launch(void* const* d_in, const int* in_sizes, int n_in,
                              void* d_out, int out_size) {
    const int*   edges   = (const int*)d_in[0];
    const int*   nps     = (const int*)d_in[1];   // nodes_p_star
    const int*   npp     = (const int*)d_in[2];   // nodes_p
    const float* beta_p  = (const float*)d_in[3];
    const float* beta_ps = (const float*)d_in[4];
    const float* p       = (const float*)d_in[5];
    const float* pstar   = (const float*)d_in[6];
    float* out = (float*)d_out;
    int E = in_sizes[0] / 2;

    cudaFuncSetAttribute(k_nonlink_mma, cudaFuncAttributeMaxDynamicSharedMemorySize, DYN_SMEM_NL);

    k_prep<<<(2 * NN + 7) / 8, 256>>>(p, pstar);
    k_gather<<<NB / 8, 256>>>(nps, npp, beta_p, beta_ps);
    k_link<<<2048, 256>>>(edges, E, beta_p, beta_ps);
    k_nonlink_mma<<<GRID_NL, 256, DYN_SMEM_NL>>>();
    k_final<<<1, 1>>>(out);
}

// round 10
// speedup vs baseline: 1.1148x; 1.0242x over previous
#include <cuda_runtime.h>
#include <cuda_bf16.h>
#include <cstdint>

#define DIMN 128
#define NB   16384
#define NN   20000
#define NT   (NB / 128)                 // 128 tile rows/cols
#define NTILES (NT * (NT + 1) / 2)      // 8256 triu tiles
#define EPSL 1e-6f
#define L2E  1.4426950408889634f
#define GRID_NL 296                     // 2 CTAs per SM
#define CHUNK ((NTILES + GRID_NL - 1) / GRID_NL)   // 28 tiles per CTA

// smem tile geometry: 128 rows x 128 bf16, padded to 136 bf16 (272 B) per row
#define ROWB 272
#define TILEB (128 * ROWB)              // 34816 B per operand tile
#define RING_OFF (3 * TILEB)            // 3 x 1KB npbp column slices
#define NSBS_OFF (RING_OFF + 3 * 1024)  // 1KB nsbs row slice
#define DYN_SMEM_NL (NSBS_OFF + 1024)   // 108544 B -> still 2 CTAs/SM

// ---- scratch (static device globals; no allocation) ----
__device__ __align__(16) __nv_bfloat16 g_p_bf[NN * DIMN];     // full p table, bf16
__device__ __align__(16) __nv_bfloat16 g_pstar_bf[NN * DIMN]; // full p_star table, bf16
__device__ __align__(16) __nv_bfloat16 g_ps_bf[NB * DIMN];    // L2E * p_star[nodes_p_star]
__device__ __align__(16) __nv_bfloat16 g_pp_bf[NB * DIMN];    // L2E * p[nodes_p]
__device__ float2   g_nsbs[NB];        // {|scaled ps row|^2, L2E*beta_p_star}
__device__ float2   g_npbp[NB];        // {|scaled pp row|^2, L2E*beta_p}
__device__ double   g_acc[2];          // [0]=link, [1]=nonlink

static __device__ __forceinline__ float sqrt_approx(float x) {
    float r; asm("sqrt.approx.f32 %0, %1;" : "=f"(r) : "f"(x)); return r;
}
static __device__ __forceinline__ float ex2_approx(float x) {
    float r; asm("ex2.approx.f32 %0, %1;" : "=f"(r) : "f"(x)); return r;
}
static __device__ __forceinline__ uint32_t smem_u32(const void* p) {
    uint32_t a;
    asm("{ .reg .u64 t; cvta.to.shared.u64 t, %1; cvt.u32.u64 %0, t; }" : "=r"(a) : "l"(p));
    return a;
}
static __device__ __forceinline__ void cp_async16(uint32_t dst, const void* src) {
    asm volatile("cp.async.cg.shared.global [%0], [%1], 16;" :: "r"(dst), "l"(src) : "memory");
}
static __device__ __forceinline__ void cp_commit() {
    asm volatile("cp.async.commit_group;" ::: "memory");
}
template <int N> static __device__ __forceinline__ void cp_wait() {
    asm volatile("cp.async.wait_group %0;" :: "n"(N) : "memory");
}
static __device__ __forceinline__ void ldsm_x4(uint32_t& r0, uint32_t& r1,
                                               uint32_t& r2, uint32_t& r3, uint32_t a) {
    asm volatile("ldmatrix.sync.aligned.m8n8.x4.shared.b16 {%0,%1,%2,%3}, [%4];"
                 : "=r"(r0), "=r"(r1), "=r"(r2), "=r"(r3) : "r"(a));
}
static __device__ __forceinline__ void mma16816(float* d, const uint32_t* a,
                                                uint32_t b0, uint32_t b1) {
    asm volatile("mma.sync.aligned.m16n8k16.row.col.f32.bf16.bf16.f32 "
                 "{%0,%1,%2,%3}, {%4,%5,%6,%7}, {%8,%9}, {%0,%1,%2,%3};"
                 : "+f"(d[0]), "+f"(d[1]), "+f"(d[2]), "+f"(d[3])
                 : "r"(a[0]), "r"(a[1]), "r"(a[2]), "r"(a[3]), "r"(b0), "r"(b1));
}
static __device__ __forceinline__ float2 bf2f(uint32_t u) {
    __nv_bfloat162 h = *reinterpret_cast<__nv_bfloat162*>(&u);
    return __bfloat1622float2(h);
}

// One epilogue slice: 4 elements (rows r_lo, r_lo+8 x cols c0, c0+1).
// cv pairs come from an smem-staged slice (LDS, no long-scoreboard stalls).
static __device__ __forceinline__ void epi_slice(
    float& nls, const float* d, const float2 rv0, const float2 rv1,
    const float2* cvp, bool diag, int r_lo, int c0) {
    const float2 cv0 = cvp[0];
    const float2 cv1 = cvp[1];
    if (!diag) {
        nls += ex2_approx(rv0.y + cv0.y - sqrt_approx(fmaxf(rv0.x + cv0.x - 2.f * d[0], 0.f)));
        nls += ex2_approx(rv0.y + cv1.y - sqrt_approx(fmaxf(rv0.x + cv1.x - 2.f * d[1], 0.f)));
        nls += ex2_approx(rv1.y + cv0.y - sqrt_approx(fmaxf(rv1.x + cv0.x - 2.f * d[2], 0.f)));
        nls += ex2_approx(rv1.y + cv1.y - sqrt_approx(fmaxf(rv1.x + cv1.x - 2.f * d[3], 0.f)));
    } else {
        float w;
        w = ex2_approx(rv0.y + cv0.y - sqrt_approx(fmaxf(rv0.x + cv0.x - 2.f * d[0], 0.f)));
        if (r_lo < c0) nls += w;
        w = ex2_approx(rv0.y + cv1.y - sqrt_approx(fmaxf(rv0.x + cv1.x - 2.f * d[1], 0.f)));
        if (r_lo < c0 + 1) nls += w;
        w = ex2_approx(rv1.y + cv0.y - sqrt_approx(fmaxf(rv1.x + cv0.x - 2.f * d[2], 0.f)));
        if (r_lo + 8 < c0) nls += w;
        w = ex2_approx(rv1.y + cv1.y - sqrt_approx(fmaxf(rv1.x + cv1.x - 2.f * d[3], 0.f)));
        if (r_lo + 8 < c0 + 1) nls += w;
    }
}

// ---------------- kernels ----------------
// convert full p / p_star tables to bf16 (one warp per row per table); zero accumulators
__global__ void k_prep(const float* __restrict__ p, const float* __restrict__ pstar) {
    if (blockIdx.x == 0 && threadIdx.x == 0) { g_acc[0] = 0.0; g_acc[1] = 0.0; }
    int w    = blockIdx.x * 8 + (threadIdx.x >> 5);
    int lane = threadIdx.x & 31;
    int row  = w >> 1;
    if (row >= NN) return;
    const float* src = (w & 1) ? pstar : p;
    __nv_bfloat16* dst = (w & 1) ? g_pstar_bf : g_p_bf;
    float4 v = ((const float4*)(src + (size_t)row * DIMN))[lane];
    __nv_bfloat162* d = (__nv_bfloat162*)(dst + (size_t)row * DIMN);
    d[2 * lane + 0] = __floats2bfloat162_rn(v.x, v.y);
    d[2 * lane + 1] = __floats2bfloat162_rn(v.z, v.w);
}

// gather rows (from bf16 tables), scale by L2E, store scaled bf16 + {norm,beta} pairs
__global__ void k_gather(const int* __restrict__ nps, const int* __restrict__ npp,
                         const float* __restrict__ beta_p, const float* __restrict__ beta_ps) {
    int row  = blockIdx.x * 8 + (threadIdx.x >> 5);
    int lane = threadIdx.x & 31;
    if (row >= NB) return;
    int is = nps[row], ip = npp[row];
    uint2 rs = ((const uint2*)(g_pstar_bf + (size_t)is * DIMN))[lane];
    uint2 rp = ((const uint2*)(g_p_bf     + (size_t)ip * DIMN))[lane];

    float2 s0 = bf2f(rs.x), s1 = bf2f(rs.y), p0 = bf2f(rp.x), p1 = bf2f(rp.y);
    __nv_bfloat162 os0 = __floats2bfloat162_rn(s0.x * L2E, s0.y * L2E);
    __nv_bfloat162 os1 = __floats2bfloat162_rn(s1.x * L2E, s1.y * L2E);
    __nv_bfloat162 op0 = __floats2bfloat162_rn(p0.x * L2E, p0.y * L2E);
    __nv_bfloat162 op1 = __floats2bfloat162_rn(p1.x * L2E, p1.y * L2E);
    ((__nv_bfloat162*)(g_ps_bf + (size_t)row * DIMN))[2 * lane + 0] = os0;
    ((__nv_bfloat162*)(g_ps_bf + (size_t)row * DIMN))[2 * lane + 1] = os1;
    ((__nv_bfloat162*)(g_pp_bf + (size_t)row * DIMN))[2 * lane + 0] = op0;
    ((__nv_bfloat162*)(g_pp_bf + (size_t)row * DIMN))[2 * lane + 1] = op1;

    float2 a0 = __bfloat1622float2(os0), a1 = __bfloat1622float2(os1);
    float2 b0 = __bfloat1622float2(op0), b1 = __bfloat1622float2(op1);
    float a = a0.x*a0.x + a0.y*a0.y + a1.x*a1.x + a1.y*a1.y;
    float b = b0.x*b0.x + b0.y*b0.y + b1.x*b1.x + b1.y*b1.y;
#pragma unroll
    for (int o = 16; o; o >>= 1) {
        a += __shfl_xor_sync(0xffffffffu, a, o);
        b += __shfl_xor_sync(0xffffffffu, b, o);
    }
    if (lane == 0) {
        g_nsbs[row] = make_float2(a, beta_ps[is] * L2E);
        g_npbp[row] = make_float2(b, beta_p[ip] * L2E);
    }
}

// Link term: 8 lanes per edge, 4 edges per warp in parallel (3-deep shfl reduce).
__global__ void k_link(const int* __restrict__ edges, int E,
                       const float* __restrict__ beta_p, const float* __restrict__ beta_ps) {
    __shared__ float wsum[8];
    const int gw   = (blockIdx.x * blockDim.x + threadIdx.x) >> 5;
    const int wid  = threadIdx.x >> 5;
    const int lane = threadIdx.x & 31;
    const int nw   = (gridDim.x * blockDim.x) >> 5;
    const int sub  = lane & 7;
    const int eq   = lane >> 3;

    float local = 0.f;
    for (int base = gw * 4; base < E; base += nw * 4) {
        const int e = base + eq;
        const bool valid = (e < E);
        float s = 0.f;
        int e0 = 0, e1 = 0;
        if (valid) {
            e0 = edges[e]; e1 = edges[E + e];
            const uint4* ra = (const uint4*)(g_p_bf     + (size_t)e0 * DIMN);
            const uint4* rb = (const uint4*)(g_pstar_bf + (size_t)e1 * DIMN);
            const uint4 a0 = ra[2 * sub], a1 = ra[2 * sub + 1];
            const uint4 b0 = rb[2 * sub], b1 = rb[2 * sub + 1];
#pragma unroll
            for (int w = 0; w < 4; w++) {
                const float2 fa = bf2f((&a0.x)[w]), fb = bf2f((&b0.x)[w]);
                const float dx = fa.x - fb.x + EPSL, dy = fa.y - fb.y + EPSL;
                s += dx * dx + dy * dy;
            }
#pragma unroll
            for (int w = 0; w < 4; w++) {
                const float2 fa = bf2f((&a1.x)[w]), fb = bf2f((&b1.x)[w]);
                const float dx = fa.x - fb.x + EPSL, dy = fa.y - fb.y + EPSL;
                s += dx * dx + dy * dy;
            }
        }
        s += __shfl_xor_sync(0xffffffffu, s, 1);
        s += __shfl_xor_sync(0xffffffffu, s, 2);
        s += __shfl_xor_sync(0xffffffffu, s, 4);
        if (valid && sub == 0)
            local += beta_ps[e0] + beta_p[e1] - sqrt_approx(s);
    }
#pragma unroll
    for (int o = 16; o; o >>= 1) local += __shfl_xor_sync(0xffffffffu, local, o);
    if (lane == 0) wsum[wid] = local;
    __syncthreads();
    if (threadIdx.x == 0) {
        float s = 0.f;
#pragma unroll
        for (int w = 0; w < 8; w++) s += wsum[w];
        atomicAdd(&g_acc[0], (double)s);
    }
}

// Non-link: persistent mma.sync bf16 GEMM, 8 warps x 32x64, 2 CTAs/SM, A persists
// across same-row tiles, B double-buffered, half-tile software-pipelined epilogue.
// Epilogue row/col vectors staged in smem (npbp: 3-slot ring with B; nsbs with A)
// so the interleaved slices issue LDS, not LDG.
__global__ __launch_bounds__(256, 2)
void k_nonlink_mma() {
    extern __shared__ __align__(16) char smem[];
    __shared__ float warpsum[8];
    const int tid  = threadIdx.x;
    const int wid  = tid >> 5;
    const int lane = tid & 31;
    const uint32_t sbase = smem_u32(smem);
    const uint32_t abase = sbase;
    const uint32_t bst[2] = { sbase + TILEB, sbase + 2 * TILEB };
    const float2* const s_ring = (const float2*)(smem + RING_OFF);   // 3 x 128 float2
    const float2* const s_ns   = (const float2*)(smem + NSBS_OFF);   // 128 float2

    const int row0w = (wid & 3) * 32;     // 4 M-strips of 32
    const int col0w = (wid >> 2) * 64;    // 2 N-strips of 64 (2 halves of 32)
    const uint32_t lm_off = (uint32_t)(lane & 15) * ROWB + (uint32_t)(lane >> 4) * 16;
    const int lq = 2 * (lane & 3);        // lane's col offset within an n8 group
    const int lr = lane >> 2;             // lane's row offset

    float nls = 0.f;

    const int t0 = blockIdx.x * CHUNK;
    const int t1 = (t0 + CHUNK < NTILES) ? (t0 + CHUNK) : NTILES;

    // ping-pong accumulators: accH[0]=half0 of current tile, accH[1]=half1
    float accH[2][2][4][4];
    // carried prev-half state (always tile t-1's half1)
    float2 rvP[4];
    const float2* pnp = s_ring;           // prev tile's npbp slice
    int  prl = 0, pcb = 0;
    bool pdiag = false, pvalid = false;

    if (t0 < t1) {
        int by = 0, rem = t0;
        while (rem >= NT - by) { rem -= NT - by; by++; }
        int bx = by + rem;
        int slot = t0 % 3;

        // prologue: A(by) + nsbs(by) + B(bx) + npbp(bx) into stage 0 / ring slot
#pragma unroll
        for (int it = 0; it < 8; it++) {
            const int c = tid + (it << 8);
            const int m = c >> 4, q = c & 15;
            cp_async16(abase + (uint32_t)m * ROWB + (uint32_t)q * 16,
                       (const char*)g_ps_bf + ((size_t)((by << 7) + m) << 8) + ((size_t)q << 4));
            cp_async16(bst[0] + (uint32_t)m * ROWB + (uint32_t)q * 16,
                       (const char*)g_pp_bf + ((size_t)((bx << 7) + m) << 8) + ((size_t)q << 4));
        }
        if (tid < 64)
            cp_async16(sbase + RING_OFF + (uint32_t)slot * 1024 + (uint32_t)tid * 16,
                       (const char*)g_npbp + ((size_t)bx << 10) + ((size_t)tid << 4));
        else if (tid < 128)
            cp_async16(sbase + NSBS_OFF + (uint32_t)(tid - 64) * 16,
                       (const char*)g_nsbs + ((size_t)by << 10) + ((size_t)(tid - 64) << 4));
        cp_commit();

        int s = 0;
        for (int t = t0; t < t1; t++) {
            int nbx = bx + 1, nby = by;
            if (nbx >= NT) { nby = by + 1; nbx = nby; }
            const int nslot = (slot + 1 == 3) ? 0 : slot + 1;
            const bool have_next = (t + 1 < t1);

            if (have_next) {
#pragma unroll
                for (int it = 0; it < 8; it++) {
                    const int c = tid + (it << 8);
                    const int m = c >> 4, q = c & 15;
                    cp_async16(bst[1 - s] + (uint32_t)m * ROWB + (uint32_t)q * 16,
                               (const char*)g_pp_bf + ((size_t)((nbx << 7) + m) << 8) + ((size_t)q << 4));
                }
                if (tid < 64)
                    cp_async16(sbase + RING_OFF + (uint32_t)nslot * 1024 + (uint32_t)tid * 16,
                               (const char*)g_npbp + ((size_t)nbx << 10) + ((size_t)tid << 4));
            }
            cp_commit();
            cp_wait<1>();
            __syncthreads();

            // row-side values for the CURRENT tile (LDS from staged slice)
            const int crl = (by << 7) + row0w + lr;
            float2 rvC[4];
            rvC[0] = s_ns[row0w + lr];      rvC[1] = s_ns[row0w + lr + 8];
            rvC[2] = s_ns[row0w + lr + 16]; rvC[3] = s_ns[row0w + lr + 24];

            const uint32_t aw = abase  + (uint32_t)row0w * ROWB + lm_off;
            const uint32_t bw = bst[s] + (uint32_t)col0w * ROWB + lm_off;
            const bool cdiag = (bx == by);
            const int  ccb0  = (bx << 7) + col0w + lq;          // current half0 global col base
            const float2* const cnp = s_ring + slot * 128;      // current tile's npbp slice

#pragma unroll
            for (int h = 0; h < 2; h++) {
                float (*cur)[4][4] = accH[h];
#pragma unroll
                for (int mi = 0; mi < 2; mi++)
#pragma unroll
                    for (int n = 0; n < 4; n++)
#pragma unroll
                        for (int v = 0; v < 4; v++) cur[mi][n][v] = 0.f;

                const uint32_t bwh = bw + (uint32_t)h * 32 * ROWB;
                const bool do_epi = (h == 1) || pvalid;

#pragma unroll
                for (int k = 0; k < 8; k++) {
                    uint32_t a[2][4], bf[2][4];
#pragma unroll
                    for (int mi = 0; mi < 2; mi++)
                        ldsm_x4(a[mi][0], a[mi][1], a[mi][2], a[mi][3],
                                aw + (uint32_t)mi * 16 * ROWB + (uint32_t)k * 32);
#pragma unroll
                    for (int nj = 0; nj < 2; nj++)
                        ldsm_x4(bf[nj][0], bf[nj][1], bf[nj][2], bf[nj][3],
                                bwh + (uint32_t)nj * 16 * ROWB + (uint32_t)k * 32);
#pragma unroll
                    for (int mi = 0; mi < 2; mi++)
#pragma unroll
                        for (int n = 0; n < 4; n++) {
                            const int nj = n >> 1;
                            if ((n & 1) == 0) mma16816(cur[mi][n], a[mi], bf[nj][0], bf[nj][2]);
                            else              mma16816(cur[mi][n], a[mi], bf[nj][1], bf[nj][3]);
                        }
                    // interleaved epilogue slice of the previous 32x32 half (LDS only)
                    if (do_epi) {
                        const int emi = k >> 2, en = k & 3;
                        if (h == 0) {
                            epi_slice(nls, accH[1][emi][en], rvP[emi * 2], rvP[emi * 2 + 1],
                                      pnp + (col0w + 32 + lq) + en * 8, pdiag,
                                      prl + emi * 16, pcb + en * 8);
                        } else {
                            epi_slice(nls, accH[0][emi][en], rvC[emi * 2], rvC[emi * 2 + 1],
                                      cnp + (col0w + lq) + en * 8, cdiag,
                                      crl + emi * 16, ccb0 + en * 8);
                        }
                    }
                }
            }
            __syncthreads();    // all warps done with A + B stage s + staged slices

            if (have_next && nby != by) {   // A + nsbs refill for next row
#pragma unroll
                for (int it = 0; it < 8; it++) {
                    const int c = tid + (it << 8);
                    const int m = c >> 4, q = c & 15;
                    cp_async16(abase + (uint32_t)m * ROWB + (uint32_t)q * 16,
                               (const char*)g_ps_bf + ((size_t)((nby << 7) + m) << 8) + ((size_t)q << 4));
                }
                if (tid < 64)
                    cp_async16(sbase + NSBS_OFF + (uint32_t)tid * 16,
                               (const char*)g_nsbs + ((size_t)nby << 10) + ((size_t)tid << 4));
                cp_commit();
            }

            // carry prev-half state = current tile's half1
            rvP[0] = rvC[0]; rvP[1] = rvC[1]; rvP[2] = rvC[2]; rvP[3] = rvC[3];
            pnp = cnp; prl = crl; pcb = ccb0 + 32; pdiag = cdiag; pvalid = true;
            by = nby; bx = nbx; s ^= 1; slot = nslot;
        }

        // drain: epilogue of the final tile's half1 (ring slot untouched after loop)
#pragma unroll
        for (int k = 0; k < 8; k++) {
            const int emi = k >> 2, en = k & 3;
            epi_slice(nls, accH[1][emi][en], rvP[emi * 2], rvP[emi * 2 + 1],
                      pnp + (col0w + 32 + lq) + en * 8, pdiag,
                      prl + emi * 16, pcb + en * 8);
        }
    }

#pragma unroll
    for (int o = 16; o; o >>= 1) nls += __shfl_xor_sync(0xffffffffu, nls, o);
    if (lane == 0) warpsum[wid] = nls;
    __syncthreads();
    if (tid == 0) {
        float sum = 0.f;
#pragma unroll
        for (int w = 0; w < 8; w++) sum += warpsum[w];
        atomicAdd(&g_acc[1], (double)sum);
    }
}

__global__ void k_final(float* out) {
    out[0] = (float)(g_acc[1] - g_acc[0]);   // -(link - nonlink)
}

extern "C" void kernel_launch(void* const* d_in, const int* in_sizes, int n_in,
                              void* d_out, int out_size) {
    const int*   edges   = (const int*)d_in[0];
    const int*   nps     = (const int*)d_in[1];   // nodes_p_star
    const int*   npp     = (const int*)d_in[2];   // nodes_p
    const float* beta_p  = (const float*)d_in[3];
    const float* beta_ps = (const float*)d_in[4];
    const float* p       = (const float*)d_in[5];
    const float* pstar   = (const float*)d_in[6];
    float* out = (float*)d_out;
    int E = in_sizes[0] / 2;

    cudaFuncSetAttribute(k_nonlink_mma, cudaFuncAttributeMaxDynamicSharedMemorySize, DYN_SMEM_NL);

    k_prep<<<(2 * NN + 7) / 8, 256>>>(p, pstar);
    k_gather<<<NB / 8, 256>>>(nps, npp, beta_p, beta_ps);
    k_link<<<2048, 256>>>(edges, E, beta_p, beta_ps);
    k_nonlink_mma<<<GRID_NL, 256, DYN_SMEM_NL>>>();
    k_final<<<1, 1>>>(out);
}

// round 11
// speedup vs baseline: 1.1728x; 1.0520x over previous
#include <cuda_runtime.h>
#include <cuda_bf16.h>
#include <cstdint>

#define DIMN 128
#define NB   16384
#define NN   20000
#define NTX  256                        // 64-wide col tiles
#define NTILES2 16512                   // sum over by of (256 - 2*by)
#define EPSL 1e-6f
#define L2E  1.4426950408889634f
#define GRID_NL 444                     // 3 CTAs per SM
#define CHUNK ((NTILES2 + GRID_NL - 1) / GRID_NL)   // 38

// smem geometry: rows padded to 272 B (136 bf16)
#define ROWB 272
#define TILEB_A (128 * ROWB)            // 34816
#define TILEB_B (64 * ROWB)             // 17408
#define RING_OFF (TILEB_A + 2 * TILEB_B)        // 69632; 3 x 512B npbp slices
#define NSBS_OFF (RING_OFF + 3 * 512)           // 71168; 1KB nsbs row slice
#define DYN_SMEM_NL (NSBS_OFF + 1024)           // 72192 B -> 3 CTAs/SM

// ---- scratch (static device globals; no allocation) ----
__device__ __align__(16) __nv_bfloat16 g_p_bf[NN * DIMN];     // full p table, bf16
__device__ __align__(16) __nv_bfloat16 g_pstar_bf[NN * DIMN]; // full p_star table, bf16
__device__ __align__(16) __nv_bfloat16 g_ps_bf[NB * DIMN];    // L2E * p_star[nodes_p_star]
__device__ __align__(16) __nv_bfloat16 g_pp_bf[NB * DIMN];    // L2E * p[nodes_p]
__device__ float2   g_nsbs[NB];        // {|scaled ps row|^2, L2E*beta_p_star}
__device__ float2   g_npbp[NB];        // {|scaled pp row|^2, L2E*beta_p}
__device__ double   g_acc[2];          // [0]=link, [1]=nonlink

static __device__ __forceinline__ float sqrt_approx(float x) {
    float r; asm("sqrt.approx.f32 %0, %1;" : "=f"(r) : "f"(x)); return r;
}
static __device__ __forceinline__ float ex2_approx(float x) {
    float r; asm("ex2.approx.f32 %0, %1;" : "=f"(r) : "f"(x)); return r;
}
static __device__ __forceinline__ uint32_t smem_u32(const void* p) {
    uint32_t a;
    asm("{ .reg .u64 t; cvta.to.shared.u64 t, %1; cvt.u32.u64 %0, t; }" : "=r"(a) : "l"(p));
    return a;
}
static __device__ __forceinline__ void cp_async16(uint32_t dst, const void* src) {
    asm volatile("cp.async.cg.shared.global [%0], [%1], 16;" :: "r"(dst), "l"(src) : "memory");
}
static __device__ __forceinline__ void cp_commit() {
    asm volatile("cp.async.commit_group;" ::: "memory");
}
template <int N> static __device__ __forceinline__ void cp_wait() {
    asm volatile("cp.async.wait_group %0;" :: "n"(N) : "memory");
}
static __device__ __forceinline__ void ldsm_x4(uint32_t& r0, uint32_t& r1,
                                               uint32_t& r2, uint32_t& r3, uint32_t a) {
    asm volatile("ldmatrix.sync.aligned.m8n8.x4.shared.b16 {%0,%1,%2,%3}, [%4];"
                 : "=r"(r0), "=r"(r1), "=r"(r2), "=r"(r3) : "r"(a));
}
static __device__ __forceinline__ void mma16816(float* d, const uint32_t* a,
                                                uint32_t b0, uint32_t b1) {
    asm volatile("mma.sync.aligned.m16n8k16.row.col.f32.bf16.bf16.f32 "
                 "{%0,%1,%2,%3}, {%4,%5,%6,%7}, {%8,%9}, {%0,%1,%2,%3};"
                 : "+f"(d[0]), "+f"(d[1]), "+f"(d[2]), "+f"(d[3])
                 : "r"(a[0]), "r"(a[1]), "r"(a[2]), "r"(a[3]), "r"(b0), "r"(b1));
}
static __device__ __forceinline__ float2 bf2f(uint32_t u) {
    __nv_bfloat162 h = *reinterpret_cast<__nv_bfloat162*>(&u);
    return __bfloat1622float2(h);
}

// One epilogue slice: 4 elements (rows r_lo, r_lo+8 x cols c0, c0+1).
// cv pairs come from an smem-staged slice (LDS).
static __device__ __forceinline__ void epi_slice(
    float& nls, const float* d, const float2 rv0, const float2 rv1,
    const float2* cvp, bool diag, int r_lo, int c0) {
    const float2 cv0 = cvp[0];
    const float2 cv1 = cvp[1];
    if (!diag) {
        nls += ex2_approx(rv0.y + cv0.y - sqrt_approx(fmaxf(rv0.x + cv0.x - 2.f * d[0], 0.f)));
        nls += ex2_approx(rv0.y + cv1.y - sqrt_approx(fmaxf(rv0.x + cv1.x - 2.f * d[1], 0.f)));
        nls += ex2_approx(rv1.y + cv0.y - sqrt_approx(fmaxf(rv1.x + cv0.x - 2.f * d[2], 0.f)));
        nls += ex2_approx(rv1.y + cv1.y - sqrt_approx(fmaxf(rv1.x + cv1.x - 2.f * d[3], 0.f)));
    } else {
        float w;
        w = ex2_approx(rv0.y + cv0.y - sqrt_approx(fmaxf(rv0.x + cv0.x - 2.f * d[0], 0.f)));
        if (r_lo < c0) nls += w;
        w = ex2_approx(rv0.y + cv1.y - sqrt_approx(fmaxf(rv0.x + cv1.x - 2.f * d[1], 0.f)));
        if (r_lo < c0 + 1) nls += w;
        w = ex2_approx(rv1.y + cv0.y - sqrt_approx(fmaxf(rv1.x + cv0.x - 2.f * d[2], 0.f)));
        if (r_lo + 8 < c0) nls += w;
        w = ex2_approx(rv1.y + cv1.y - sqrt_approx(fmaxf(rv1.x + cv1.x - 2.f * d[3], 0.f)));
        if (r_lo + 8 < c0 + 1) nls += w;
    }
}

// ---------------- kernels ----------------
// convert full p / p_star tables to bf16 (one warp per row per table); zero accumulators
__global__ void k_prep(const float* __restrict__ p, const float* __restrict__ pstar) {
    if (blockIdx.x == 0 && threadIdx.x == 0) { g_acc[0] = 0.0; g_acc[1] = 0.0; }
    int w    = blockIdx.x * 8 + (threadIdx.x >> 5);
    int lane = threadIdx.x & 31;
    int row  = w >> 1;
    if (row >= NN) return;
    const float* src = (w & 1) ? pstar : p;
    __nv_bfloat16* dst = (w & 1) ? g_pstar_bf : g_p_bf;
    float4 v = ((const float4*)(src + (size_t)row * DIMN))[lane];
    __nv_bfloat162* d = (__nv_bfloat162*)(dst + (size_t)row * DIMN);
    d[2 * lane + 0] = __floats2bfloat162_rn(v.x, v.y);
    d[2 * lane + 1] = __floats2bfloat162_rn(v.z, v.w);
}

// gather rows (from bf16 tables), scale by L2E, store scaled bf16 + {norm,beta} pairs
__global__ void k_gather(const int* __restrict__ nps, const int* __restrict__ npp,
                         const float* __restrict__ beta_p, const float* __restrict__ beta_ps) {
    int row  = blockIdx.x * 8 + (threadIdx.x >> 5);
    int lane = threadIdx.x & 31;
    if (row >= NB) return;
    int is = nps[row], ip = npp[row];
    uint2 rs = ((const uint2*)(g_pstar_bf + (size_t)is * DIMN))[lane];
    uint2 rp = ((const uint2*)(g_p_bf     + (size_t)ip * DIMN))[lane];

    float2 s0 = bf2f(rs.x), s1 = bf2f(rs.y), p0 = bf2f(rp.x), p1 = bf2f(rp.y);
    __nv_bfloat162 os0 = __floats2bfloat162_rn(s0.x * L2E, s0.y * L2E);
    __nv_bfloat162 os1 = __floats2bfloat162_rn(s1.x * L2E, s1.y * L2E);
    __nv_bfloat162 op0 = __floats2bfloat162_rn(p0.x * L2E, p0.y * L2E);
    __nv_bfloat162 op1 = __floats2bfloat162_rn(p1.x * L2E, p1.y * L2E);
    ((__nv_bfloat162*)(g_ps_bf + (size_t)row * DIMN))[2 * lane + 0] = os0;
    ((__nv_bfloat162*)(g_ps_bf + (size_t)row * DIMN))[2 * lane + 1] = os1;
    ((__nv_bfloat162*)(g_pp_bf + (size_t)row * DIMN))[2 * lane + 0] = op0;
    ((__nv_bfloat162*)(g_pp_bf + (size_t)row * DIMN))[2 * lane + 1] = op1;

    float2 a0 = __bfloat1622float2(os0), a1 = __bfloat1622float2(os1);
    float2 b0 = __bfloat1622float2(op0), b1 = __bfloat1622float2(op1);
    float a = a0.x*a0.x + a0.y*a0.y + a1.x*a1.x + a1.y*a1.y;
    float b = b0.x*b0.x + b0.y*b0.y + b1.x*b1.x + b1.y*b1.y;
#pragma unroll
    for (int o = 16; o; o >>= 1) {
        a += __shfl_xor_sync(0xffffffffu, a, o);
        b += __shfl_xor_sync(0xffffffffu, b, o);
    }
    if (lane == 0) {
        g_nsbs[row] = make_float2(a, beta_ps[is] * L2E);
        g_npbp[row] = make_float2(b, beta_p[ip] * L2E);
    }
}

// Link term: 8 lanes per edge, 4 edges per warp in parallel (3-deep shfl reduce).
__global__ void k_link(const int* __restrict__ edges, int E,
                       const float* __restrict__ beta_p, const float* __restrict__ beta_ps) {
    __shared__ float wsum[8];
    const int gw   = (blockIdx.x * blockDim.x + threadIdx.x) >> 5;
    const int wid  = threadIdx.x >> 5;
    const int lane = threadIdx.x & 31;
    const int nw   = (gridDim.x * blockDim.x) >> 5;
    const int sub  = lane & 7;
    const int eq   = lane >> 3;

    float local = 0.f;
    for (int base = gw * 4; base < E; base += nw * 4) {
        const int e = base + eq;
        const bool valid = (e < E);
        float s = 0.f;
        int e0 = 0, e1 = 0;
        if (valid) {
            e0 = edges[e]; e1 = edges[E + e];
            const uint4* ra = (const uint4*)(g_p_bf     + (size_t)e0 * DIMN);
            const uint4* rb = (const uint4*)(g_pstar_bf + (size_t)e1 * DIMN);
            const uint4 a0 = ra[2 * sub], a1 = ra[2 * sub + 1];
            const uint4 b0 = rb[2 * sub], b1 = rb[2 * sub + 1];
#pragma unroll
            for (int w = 0; w < 4; w++) {
                const float2 fa = bf2f((&a0.x)[w]), fb = bf2f((&b0.x)[w]);
                const float dx = fa.x - fb.x + EPSL, dy = fa.y - fb.y + EPSL;
                s += dx * dx + dy * dy;
            }
#pragma unroll
            for (int w = 0; w < 4; w++) {
                const float2 fa = bf2f((&a1.x)[w]), fb = bf2f((&b1.x)[w]);
                const float dx = fa.x - fb.x + EPSL, dy = fa.y - fb.y + EPSL;
                s += dx * dx + dy * dy;
            }
        }
        s += __shfl_xor_sync(0xffffffffu, s, 1);
        s += __shfl_xor_sync(0xffffffffu, s, 2);
        s += __shfl_xor_sync(0xffffffffu, s, 4);
        if (valid && sub == 0)
            local += beta_ps[e0] + beta_p[e1] - sqrt_approx(s);
    }
#pragma unroll
    for (int o = 16; o; o >>= 1) local += __shfl_xor_sync(0xffffffffu, local, o);
    if (lane == 0) wsum[wid] = local;
    __syncthreads();
    if (threadIdx.x == 0) {
        float s = 0.f;
#pragma unroll
        for (int w = 0; w < 8; w++) s += wsum[w];
        atomicAdd(&g_acc[0], (double)s);
    }
}

// Non-link: persistent mma.sync bf16 GEMM over 128x64 triu tiles, 3 CTAs/SM.
// 8 warps x 32x32 strips; A (128 rows) persists across same-row tiles;
// B (64 rows) double-buffered; epilogue vectors staged in smem (LDS only).
__global__ __launch_bounds__(256, 3)
void k_nonlink_mma() {
    extern __shared__ __align__(16) char smem[];
    __shared__ float warpsum[8];
    const int tid  = threadIdx.x;
    const int wid  = tid >> 5;
    const int lane = tid & 31;
    const uint32_t sbase = smem_u32(smem);
    const uint32_t abase = sbase;
    const uint32_t bst[2] = { sbase + TILEB_A, sbase + TILEB_A + TILEB_B };
    const float2* const s_ring = (const float2*)(smem + RING_OFF);   // 3 x 64 float2
    const float2* const s_ns   = (const float2*)(smem + NSBS_OFF);   // 128 float2

    const int row0w = (wid & 3) * 32;     // 4 M-strips of 32
    const int col0w = (wid >> 2) * 32;    // 2 N-strips of 32
    const uint32_t lm_off = (uint32_t)(lane & 15) * ROWB + (uint32_t)(lane >> 4) * 16;
    const int lq = 2 * (lane & 3);
    const int lr = lane >> 2;

    float nls = 0.f;

    const int t0 = blockIdx.x * CHUNK;
    const int t1 = (t0 + CHUNK < NTILES2) ? (t0 + CHUNK) : NTILES2;

    if (t0 < t1) {
        // decode t0 -> (by, bx): row by has NTX - 2*by tiles, bx in [2*by, NTX)
        int by = 0, rem = t0;
        while (rem >= NTX - 2 * by) { rem -= NTX - 2 * by; by++; }
        int bx = 2 * by + rem;
        int slot = 0;

        // prologue: A(by) + nsbs(by) + B(bx) + npbp(bx)
#pragma unroll
        for (int it = 0; it < 8; it++) {
            const int c = tid + (it << 8);
            const int m = c >> 4, q = c & 15;
            cp_async16(abase + (uint32_t)m * ROWB + (uint32_t)q * 16,
                       (const char*)g_ps_bf + ((size_t)((by << 7) + m) << 8) + ((size_t)q << 4));
        }
#pragma unroll
        for (int it = 0; it < 4; it++) {
            const int c = tid + (it << 8);
            const int m = c >> 4, q = c & 15;
            cp_async16(bst[0] + (uint32_t)m * ROWB + (uint32_t)q * 16,
                       (const char*)g_pp_bf + ((size_t)((bx << 6) + m) << 8) + ((size_t)q << 4));
        }
        if (tid < 32)
            cp_async16(sbase + RING_OFF + (uint32_t)tid * 16,
                       (const char*)g_npbp + ((size_t)bx << 9) + ((size_t)tid << 4));
        else if (tid < 96)
            cp_async16(sbase + NSBS_OFF + (uint32_t)(tid - 32) * 16,
                       (const char*)g_nsbs + ((size_t)by << 10) + ((size_t)(tid - 32) << 4));
        cp_commit();

        int s = 0;
        for (int t = t0; t < t1; t++) {
            int nbx = bx + 1, nby = by;
            if (nbx >= NTX) { nby = by + 1; nbx = 2 * nby; }
            const int nslot = (slot + 1 == 3) ? 0 : slot + 1;
            const bool have_next = (t + 1 < t1);

            if (have_next) {
#pragma unroll
                for (int it = 0; it < 4; it++) {
                    const int c = tid + (it << 8);
                    const int m = c >> 4, q = c & 15;
                    cp_async16(bst[1 - s] + (uint32_t)m * ROWB + (uint32_t)q * 16,
                               (const char*)g_pp_bf + ((size_t)((nbx << 6) + m) << 8) + ((size_t)q << 4));
                }
                if (tid < 32)
                    cp_async16(sbase + RING_OFF + (uint32_t)nslot * 512 + (uint32_t)tid * 16,
                               (const char*)g_npbp + ((size_t)nbx << 9) + ((size_t)tid << 4));
            }
            cp_commit();
            cp_wait<1>();
            __syncthreads();

            const uint32_t aw = abase  + (uint32_t)row0w * ROWB + lm_off;
            const uint32_t bw = bst[s] + (uint32_t)col0w * ROWB + lm_off;

            float acc[2][4][4];
#pragma unroll
            for (int mi = 0; mi < 2; mi++)
#pragma unroll
                for (int n = 0; n < 4; n++)
#pragma unroll
                    for (int v = 0; v < 4; v++) acc[mi][n][v] = 0.f;

#pragma unroll
            for (int k = 0; k < 8; k++) {
                uint32_t a[2][4], bf[2][4];
#pragma unroll
                for (int mi = 0; mi < 2; mi++)
                    ldsm_x4(a[mi][0], a[mi][1], a[mi][2], a[mi][3],
                            aw + (uint32_t)mi * 16 * ROWB + (uint32_t)k * 32);
#pragma unroll
                for (int nj = 0; nj < 2; nj++)
                    ldsm_x4(bf[nj][0], bf[nj][1], bf[nj][2], bf[nj][3],
                            bw + (uint32_t)nj * 16 * ROWB + (uint32_t)k * 32);
#pragma unroll
                for (int mi = 0; mi < 2; mi++)
#pragma unroll
                    for (int n = 0; n < 4; n++) {
                        const int nj = n >> 1;
                        if ((n & 1) == 0) mma16816(acc[mi][n], a[mi], bf[nj][0], bf[nj][2]);
                        else              mma16816(acc[mi][n], a[mi], bf[nj][1], bf[nj][3]);
                    }
            }

            // batched epilogue (LDS-staged vectors; values pre-scaled by L2E)
            {
                const int crl = (by << 7) + row0w + lr;
                float2 rv[4];
                rv[0] = s_ns[row0w + lr];      rv[1] = s_ns[row0w + lr + 8];
                rv[2] = s_ns[row0w + lr + 16]; rv[3] = s_ns[row0w + lr + 24];
                const float2* const cnp = s_ring + slot * 64;
                const int cb = (bx << 6) + col0w + lq;
                const bool diag = ((bx >> 1) == by);
#pragma unroll
                for (int mi = 0; mi < 2; mi++)
#pragma unroll
                    for (int n = 0; n < 4; n++)
                        epi_slice(nls, acc[mi][n], rv[mi * 2], rv[mi * 2 + 1],
                                  cnp + col0w + lq + n * 8, diag,
                                  crl + mi * 16, cb + n * 8);
            }
            __syncthreads();    // done with A, B stage s, ring slot, nsbs

            if (have_next && nby != by) {   // A + nsbs refill for next row
#pragma unroll
                for (int it = 0; it < 8; it++) {
                    const int c = tid + (it << 8);
                    const int m = c >> 4, q = c & 15;
                    cp_async16(abase + (uint32_t)m * ROWB + (uint32_t)q * 16,
                               (const char*)g_ps_bf + ((size_t)((nby << 7) + m) << 8) + ((size_t)q << 4));
                }
                if (tid < 64)
                    cp_async16(sbase + NSBS_OFF + (uint32_t)tid * 16,
                               (const char*)g_nsbs + ((size_t)nby << 10) + ((size_t)tid << 4));
                cp_commit();
            }

            by = nby; bx = nbx; s ^= 1; slot = nslot;
        }
    }

#pragma unroll
    for (int o = 16; o; o >>= 1) nls += __shfl_xor_sync(0xffffffffu, nls, o);
    if (lane == 0) warpsum[wid] = nls;
    __syncthreads();
    if (tid == 0) {
        float sum = 0.f;
#pragma unroll
        for (int w = 0; w < 8; w++) sum += warpsum[w];
        atomicAdd(&g_acc[1], (double)sum);
    }
}

__global__ void k_final(float* out) {
    out[0] = (float)(g_acc[1] - g_acc[0]);   // -(link - nonlink)
}

extern "C" void kernel_launch(void* const* d_in, const int* in_sizes, int n_in,
                              void* d_out, int out_size) {
    const int*   edges   = (const int*)d_in[0];
    const int*   nps     = (const int*)d_in[1];   // nodes_p_star
    const int*   npp     = (const int*)d_in[2];   // nodes_p
    const float* beta_p  = (const float*)d_in[3];
    const float* beta_ps = (const float*)d_in[4];
    const float* p       = (const float*)d_in[5];
    const float* pstar   = (const float*)d_in[6];
    float* out = (float*)d_out;
    int E = in_sizes[0] / 2;

    cudaFuncSetAttribute(k_nonlink_mma, cudaFuncAttributeMaxDynamicSharedMemorySize, DYN_SMEM_NL);

    k_prep<<<(2 * NN + 7) / 8, 256>>>(p, pstar);
    k_gather<<<NB / 8, 256>>>(nps, npp, beta_p, beta_ps);
    k_link<<<2048, 256>>>(edges, E, beta_p, beta_ps);
    k_nonlink_mma<<<GRID_NL, 256, DYN_SMEM_NL>>>();
    k_final<<<1, 1>>>(out);
}